// round 8
// baseline (speedup 1.0000x reference)
#include <cuda_runtime.h>
#include <cstdint>

// ---------------------------------------------------------------------------
// DoubleAttention via mma.sync tf32, R5.
// vs R4: BK=32 (two 16-k groups of the R4 conflict-free layouts), 3-stage
// cp.async pipeline in dynamic SMEM (99KB) -> half the barriers, 2-deep
// prefetch. Numerics identical to R4 (pre-rounded tf32 everywhere).
// ---------------------------------------------------------------------------

#define BSZ   32
#define CDIM  512
#define NDIM  1024

__device__ float g_xr [(size_t)BSZ * CDIM * NDIM];
__device__ float g_w  [4][(size_t)CDIM * CDIM];
__device__ float g_A  [(size_t)BSZ * CDIM * NDIM];
__device__ float g_Bm [(size_t)BSZ * CDIM * NDIM];
__device__ float g_Vm [(size_t)BSZ * CDIM * NDIM];
__device__ float g_G  [(size_t)BSZ * CDIM * CDIM];
__device__ float g_G2 [(size_t)BSZ * CDIM * CDIM];

__device__ __forceinline__ uint32_t smem_u32(const void* p) {
    uint32_t a;
    asm("{ .reg .u64 t; cvta.to.shared.u64 t, %1; cvt.u32.u64 %0, t; }"
        : "=r"(a) : "l"(p));
    return a;
}
__device__ __forceinline__ void cp16(uint32_t dst, const void* src) {
    asm volatile("cp.async.cg.shared.global [%0], [%1], 16;"
                 :: "r"(dst), "l"(src));
}
__device__ __forceinline__ float rna(float x) {
    float y;
    asm("cvt.rna.tf32.f32 %0, %1;" : "=f"(y) : "f"(x));
    return y;
}

// ---------------------------------------------------------------------------
__global__ __launch_bounds__(256)
void preround_kernel(const float4* __restrict__ in, float4* __restrict__ out, int n4)
{
    int i = blockIdx.x * 256 + threadIdx.x;
    if (i < n4) {
        float4 v = in[i];
        v.x = rna(v.x); v.y = rna(v.y); v.z = rna(v.z); v.w = rna(v.w);
        out[i] = v;
    }
}

__global__ __launch_bounds__(256)
void preround_w_kernel(const float4* w0, const float4* w1,
                       const float4* w2, const float4* w3,
                       float4* __restrict__ out)
{
    const float4* srcs[4] = { w0, w1, w2, w3 };
    const int n4 = CDIM * CDIM / 4;
    const float4* src = srcs[blockIdx.y];
    float4* dst = out + (size_t)blockIdx.y * n4;
    int i = blockIdx.x * 256 + threadIdx.x;
    if (i < n4) {
        float4 v = src[i];
        v.x = rna(v.x); v.y = rna(v.y); v.z = rna(v.z); v.w = rna(v.w);
        dst[i] = v;
    }
}

// ---------------------------------------------------------------------------
// GEMM: C[b][m][n] = sum_k A[m][k]*B[k][n] (TB=0) / A[m][k]*B[n][k] (TB=1)
// CTA 128x128, 256 thr, 8 warps (2x4 of 64x32), BK=32, 3-stage cp.async.
// SMEM stage: A [2 grp][128][16] @0 (16KB), B NN [2][16][136] / NT [2][128][16]
// @16384 (17408B). Stage stride 33792B; 3 stages = 101376B dynamic.
// ---------------------------------------------------------------------------
#define PBNN 136
#define STG_STRIDE 33792
#define GEMM_SMEM (3 * STG_STRIDE)

template<bool TB, bool BIAS, bool ROUND>
__global__ void __launch_bounds__(256)
mma_gemm_kernel(const float* __restrict__ Ag, size_t sAs, int lda,
                const float* __restrict__ Bg, size_t sBs, int ldb,
                const float* __restrict__ bias,
                float* __restrict__ Cg, size_t sCs, int ldc, int K)
{
    extern __shared__ char smem[];
    const uint32_t sbase = smem_u32(smem);

    const int tid  = threadIdx.x;
    const int lane = tid & 31;
    const int wid  = tid >> 5;
    const int m0   = (wid & 1) * 64;
    const int n0   = (wid >> 1) * 32;
    const int row0 = blockIdx.y * 128;
    const int col0 = blockIdx.x * 128;

    const float* A = Ag + (size_t)blockIdx.z * sAs;
    const float* B = Bg + (size_t)blockIdx.z * sBs;
    float*       C = Cg + (size_t)blockIdx.z * sCs;

    float acc[4][4][4];
#pragma unroll
    for (int i = 0; i < 4; i++)
#pragma unroll
        for (int j = 0; j < 4; j++)
#pragma unroll
            for (int r = 0; r < 4; r++) acc[i][j][r] = 0.f;

    const int nch = K >> 5;        // BK=32 chunks

    auto load_stage = [&](int s, int k0) {
        const uint32_t baseA = sbase + (uint32_t)s * STG_STRIDE;
        const uint32_t baseB = baseA + 16384u;
#pragma unroll
        for (int i = 0; i < 4; i++) {           // A: 128 rows x 8 chunks
            const int c  = tid + i * 256;
            const int r  = c >> 3;
            const int cc = c & 7;
            const int g  = cc >> 2;
            const int q  = cc & 3;
            cp16(baseA + (uint32_t)(g * 2048 + r * 16 + q * 4) * 4,
                 A + (size_t)(row0 + r) * lda + k0 + cc * 4);
        }
        if (!TB) {
#pragma unroll
            for (int i = 0; i < 4; i++) {       // B NN: 32 k-rows x 32 chunks
                const int c  = tid + i * 256;
                const int j  = c >> 5;          // 0..31
                const int cc = c & 31;
                const int g  = j >> 4;
                const int jj = j & 15;
                const int pr = ((jj & 3) << 2) | (jj >> 2);
                cp16(baseB + (uint32_t)(g * 2176 + pr * PBNN + cc * 4) * 4,
                     B + (size_t)(k0 + j) * ldb + col0 + cc * 4);
            }
        } else {
#pragma unroll
            for (int i = 0; i < 4; i++) {       // B NT: 128 n-rows x 8 chunks
                const int c  = tid + i * 256;
                const int r  = c >> 3;
                const int cc = c & 7;
                const int g  = cc >> 2;
                const int q  = cc & 3;
                cp16(baseB + (uint32_t)(g * 2048 + r * 16 + q * 4) * 4,
                     B + (size_t)(col0 + r) * ldb + k0 + cc * 4);
            }
        }
        asm volatile("cp.async.commit_group;" ::: "memory");
    };

    load_stage(0, 0);
    if (nch > 1) load_stage(1, 32);
    else         asm volatile("cp.async.commit_group;" ::: "memory"); // keep group count sane

    const int lr = lane >> 2;
    const int lc = lane & 3;

    for (int ch = 0; ch < nch; ++ch) {
        const int s = ch % 3;
        if (ch + 1 < nch)
            asm volatile("cp.async.wait_group 1;" ::: "memory");
        else
            asm volatile("cp.async.wait_group 0;" ::: "memory");
        __syncthreads();

        if (ch + 2 < nch) load_stage((ch + 2) % 3, (ch + 2) << 5);

        const float* sA = (const float*)(smem + (size_t)s * STG_STRIDE);
        const float* sB = (const float*)(smem + (size_t)s * STG_STRIDE + 16384);

#pragma unroll
        for (int g = 0; g < 2; g++) {
            const float* pAg = sA + g * 2048;
            float4 a0[4], a8[4];
#pragma unroll
            for (int mi = 0; mi < 4; mi++) {
                a0[mi] = *(const float4*)&pAg[(m0 + mi * 16 + lr)     * 16 + lc * 4];
                a8[mi] = *(const float4*)&pAg[(m0 + mi * 16 + lr + 8) * 16 + lc * 4];
            }
            float4 bf[4];
#pragma unroll
            for (int nj = 0; nj < 4; nj++) {
                if (TB) {
                    bf[nj] = *(const float4*)&sB[g * 2048 + (n0 + nj * 8 + lr) * 16 + lc * 4];
                } else {
                    const float* pBg = sB + g * 2176;
                    const int n = n0 + nj * 8 + lr;
                    bf[nj].x = pBg[(lc)      * PBNN + n];
                    bf[nj].y = pBg[(4 + lc)  * PBNN + n];
                    bf[nj].z = pBg[(8 + lc)  * PBNN + n];
                    bf[nj].w = pBg[(12 + lc) * PBNN + n];
                }
            }
#pragma unroll
            for (int nj = 0; nj < 4; nj++)
#pragma unroll
                for (int mi = 0; mi < 4; mi++) {
                    asm volatile(
                        "mma.sync.aligned.m16n8k8.row.col.f32.tf32.tf32.f32 "
                        "{%0,%1,%2,%3}, {%4,%5,%6,%7}, {%8,%9}, {%0,%1,%2,%3};"
                        : "+f"(acc[mi][nj][0]), "+f"(acc[mi][nj][1]),
                          "+f"(acc[mi][nj][2]), "+f"(acc[mi][nj][3])
                        : "r"(__float_as_uint(a0[mi].x)), "r"(__float_as_uint(a8[mi].x)),
                          "r"(__float_as_uint(a0[mi].y)), "r"(__float_as_uint(a8[mi].y)),
                          "r"(__float_as_uint(bf[nj].x)), "r"(__float_as_uint(bf[nj].y)));
                }
#pragma unroll
            for (int nj = 0; nj < 4; nj++)
#pragma unroll
                for (int mi = 0; mi < 4; mi++) {
                    asm volatile(
                        "mma.sync.aligned.m16n8k8.row.col.f32.tf32.tf32.f32 "
                        "{%0,%1,%2,%3}, {%4,%5,%6,%7}, {%8,%9}, {%0,%1,%2,%3};"
                        : "+f"(acc[mi][nj][0]), "+f"(acc[mi][nj][1]),
                          "+f"(acc[mi][nj][2]), "+f"(acc[mi][nj][3])
                        : "r"(__float_as_uint(a0[mi].z)), "r"(__float_as_uint(a8[mi].z)),
                          "r"(__float_as_uint(a0[mi].w)), "r"(__float_as_uint(a8[mi].w)),
                          "r"(__float_as_uint(bf[nj].z)), "r"(__float_as_uint(bf[nj].w)));
                }
        }
        __syncthreads();
    }

    // ---- epilogue ----
#pragma unroll
    for (int mi = 0; mi < 4; mi++) {
        const int r = row0 + m0 + mi * 16 + lr;
        const float bv0 = BIAS ? bias[r]     : 0.f;
        const float bv8 = BIAS ? bias[r + 8] : 0.f;
#pragma unroll
        for (int nj = 0; nj < 4; nj++) {
            const int c = col0 + n0 + nj * 8 + lc * 2;
            float2 v0 = { acc[mi][nj][0] + bv0, acc[mi][nj][1] + bv0 };
            float2 v1 = { acc[mi][nj][2] + bv8, acc[mi][nj][3] + bv8 };
            if (ROUND) {
                v0.x = rna(v0.x); v0.y = rna(v0.y);
                v1.x = rna(v1.x); v1.y = rna(v1.y);
            }
            *(float2*)(C + (size_t)r * ldc + c)       = v0;
            *(float2*)(C + (size_t)(r + 8) * ldc + c) = v1;
        }
    }
}

// ---------------------------------------------------------------------------
// Fused row softmax (rows of 1024) for two arrays, in place, tf32-rounded out.
// ---------------------------------------------------------------------------
__global__ __launch_bounds__(256)
void softmax_rows_kernel(float* __restrict__ d0, float* __restrict__ d1)
{
    float* data = blockIdx.y ? d1 : d0;
    float* row = data + (size_t)blockIdx.x * NDIM;
    const int tid = threadIdx.x;

    float4 v = *(const float4*)(row + tid * 4);

    float m = fmaxf(fmaxf(v.x, v.y), fmaxf(v.z, v.w));
#pragma unroll
    for (int off = 16; off > 0; off >>= 1)
        m = fmaxf(m, __shfl_xor_sync(0xffffffffu, m, off));
    __shared__ float smax[8];
    __shared__ float ssum[8];
    const int wid = tid >> 5, lid = tid & 31;
    if (lid == 0) smax[wid] = m;
    __syncthreads();
    if (wid == 0) {
        float tt = smax[lid & 7];
#pragma unroll
        for (int off = 4; off > 0; off >>= 1)
            tt = fmaxf(tt, __shfl_xor_sync(0xffffffffu, tt, off));
        if (lid == 0) smax[0] = tt;
    }
    __syncthreads();
    m = smax[0];

    v.x = __expf(v.x - m);
    v.y = __expf(v.y - m);
    v.z = __expf(v.z - m);
    v.w = __expf(v.w - m);
    float s = v.x + v.y + v.z + v.w;
#pragma unroll
    for (int off = 16; off > 0; off >>= 1)
        s += __shfl_xor_sync(0xffffffffu, s, off);
    if (lid == 0) ssum[wid] = s;
    __syncthreads();
    if (wid == 0) {
        float tt = ssum[lid & 7];
#pragma unroll
        for (int off = 4; off > 0; off >>= 1)
            tt += __shfl_xor_sync(0xffffffffu, tt, off);
        if (lid == 0) ssum[0] = tt;
    }
    __syncthreads();
    const float inv = 1.0f / ssum[0];

    v.x = rna(v.x * inv); v.y = rna(v.y * inv);
    v.z = rna(v.z * inv); v.w = rna(v.w * inv);
    *(float4*)(row + tid * 4) = v;
}

// ---------------------------------------------------------------------------
extern "C" void kernel_launch(void* const* d_in, const int* in_sizes, int n_in,
                              void* d_out, int out_size)
{
    const float* x  = (const float*)d_in[0];
    const float* wA = (const float*)d_in[1];
    const float* bA = (const float*)d_in[2];
    const float* wB = (const float*)d_in[3];
    const float* bB = (const float*)d_in[4];
    const float* wV = (const float*)d_in[5];
    const float* bV = (const float*)d_in[6];
    const float* wR = (const float*)d_in[7];
    const float* bR = (const float*)d_in[8];
    float* out = (float*)d_out;

    float *xr, *wr, *Am, *Bm, *Vm, *G, *G2;
    cudaGetSymbolAddress((void**)&xr, g_xr);
    cudaGetSymbolAddress((void**)&wr, g_w);
    cudaGetSymbolAddress((void**)&Am, g_A);
    cudaGetSymbolAddress((void**)&Bm, g_Bm);
    cudaGetSymbolAddress((void**)&Vm, g_Vm);
    cudaGetSymbolAddress((void**)&G,  g_G);
    cudaGetSymbolAddress((void**)&G2, g_G2);

    const float* wAr = wr;
    const float* wBr = wr + (size_t)CDIM * CDIM;
    const float* wVr = wr + (size_t)2 * CDIM * CDIM;
    const float* wRr = wr + (size_t)3 * CDIM * CDIM;

    const size_t sXN = (size_t)CDIM * NDIM;
    const size_t sCC = (size_t)CDIM * CDIM;

    static bool attr_done = false;
    if (!attr_done) {
        cudaFuncSetAttribute(mma_gemm_kernel<false, true,  true >, cudaFuncAttributeMaxDynamicSharedMemorySize, GEMM_SMEM);
        cudaFuncSetAttribute(mma_gemm_kernel<false, true,  false>, cudaFuncAttributeMaxDynamicSharedMemorySize, GEMM_SMEM);
        cudaFuncSetAttribute(mma_gemm_kernel<true,  false, true >, cudaFuncAttributeMaxDynamicSharedMemorySize, GEMM_SMEM);
        cudaFuncSetAttribute(mma_gemm_kernel<false, false, true >, cudaFuncAttributeMaxDynamicSharedMemorySize, GEMM_SMEM);
        attr_done = true;
    }

    dim3 blk(256);

    // 0) pre-round x and weights to tf32
    {
        const int n4x = (int)(BSZ * sXN / 4);
        preround_kernel<<<(n4x + 255) / 256, blk>>>((const float4*)x, (float4*)xr, n4x);
        const int n4w = CDIM * CDIM / 4;
        dim3 gw((n4w + 255) / 256, 4);
        preround_w_kernel<<<gw, blk>>>((const float4*)wA, (const float4*)wB,
                                       (const float4*)wV, (const float4*)wR,
                                       (float4*)wr);
    }

    // 1) Projections (NN): M=512, N=1024, K=512
    {
        dim3 g(NDIM / 128, CDIM / 128, BSZ);
        mma_gemm_kernel<false, true,  true ><<<g, blk, GEMM_SMEM>>>(wAr, 0, CDIM, xr, sXN, NDIM, bA, Am, sXN, NDIM, CDIM);
        mma_gemm_kernel<false, true,  false><<<g, blk, GEMM_SMEM>>>(wBr, 0, CDIM, xr, sXN, NDIM, bB, Bm, sXN, NDIM, CDIM);
        mma_gemm_kernel<false, true,  false><<<g, blk, GEMM_SMEM>>>(wVr, 0, CDIM, xr, sXN, NDIM, bV, Vm, sXN, NDIM, CDIM);
    }

    // 2) softmax over spatial dim
    {
        dim3 g(BSZ * CDIM, 2);
        softmax_rows_kernel<<<g, blk>>>(Bm, Vm);
    }

    // 3) G = Am @ Bm^T (NT), M=N=512, K=1024
    {
        dim3 g(CDIM / 128, CDIM / 128, BSZ);
        mma_gemm_kernel<true, false, true><<<g, blk, GEMM_SMEM>>>(Am, sXN, NDIM, Bm, sXN, NDIM, nullptr, G, sCC, CDIM, NDIM);
    }

    // 4) G2 = wR @ G (NN), M=N=K=512
    {
        dim3 g(CDIM / 128, CDIM / 128, BSZ);
        mma_gemm_kernel<false, false, true><<<g, blk, GEMM_SMEM>>>(wRr, 0, CDIM, G, sCC, CDIM, nullptr, G2, sCC, CDIM, CDIM);
    }

    // 5) out = G2 @ Vm + bR (NN), M=512, N=1024, K=512
    {
        dim3 g(NDIM / 128, CDIM / 128, BSZ);
        mma_gemm_kernel<false, true, false><<<g, blk, GEMM_SMEM>>>(G2, sCC, CDIM, Vm, sXN, NDIM, bR, out, sXN, NDIM, CDIM);
    }
}

// round 10
// speedup vs baseline: 1.1485x; 1.1485x over previous
#include <cuda_runtime.h>
#include <cstdint>

// ---------------------------------------------------------------------------
// DoubleAttention via mma.sync tf32, R6 (resubmit after infra failure).
// vs R5 (regressed): back to 2 pipeline stages -> 67.6KB SMEM, and
// __launch_bounds__(256,2) caps regs at 128, restoring 2 CTAs/SM (the R5
// loss). Keeps BK=32 (half the barriers of R4). Numerics unchanged.
// ---------------------------------------------------------------------------

#define BSZ   32
#define CDIM  512
#define NDIM  1024

__device__ float g_xr [(size_t)BSZ * CDIM * NDIM];
__device__ float g_w  [4][(size_t)CDIM * CDIM];
__device__ float g_A  [(size_t)BSZ * CDIM * NDIM];
__device__ float g_Bm [(size_t)BSZ * CDIM * NDIM];
__device__ float g_Vm [(size_t)BSZ * CDIM * NDIM];
__device__ float g_G  [(size_t)BSZ * CDIM * CDIM];
__device__ float g_G2 [(size_t)BSZ * CDIM * CDIM];

__device__ __forceinline__ uint32_t smem_u32(const void* p) {
    uint32_t a;
    asm("{ .reg .u64 t; cvta.to.shared.u64 t, %1; cvt.u32.u64 %0, t; }"
        : "=r"(a) : "l"(p));
    return a;
}
__device__ __forceinline__ void cp16(uint32_t dst, const void* src) {
    asm volatile("cp.async.cg.shared.global [%0], [%1], 16;"
                 :: "r"(dst), "l"(src));
}
__device__ __forceinline__ float rna(float x) {
    float y;
    asm("cvt.rna.tf32.f32 %0, %1;" : "=f"(y) : "f"(x));
    return y;
}

// ---------------------------------------------------------------------------
__global__ __launch_bounds__(256)
void preround_kernel(const float4* __restrict__ in, float4* __restrict__ out, int n4)
{
    int i = blockIdx.x * 256 + threadIdx.x;
    if (i < n4) {
        float4 v = in[i];
        v.x = rna(v.x); v.y = rna(v.y); v.z = rna(v.z); v.w = rna(v.w);
        out[i] = v;
    }
}

__global__ __launch_bounds__(256)
void preround_w_kernel(const float4* w0, const float4* w1,
                       const float4* w2, const float4* w3,
                       float4* __restrict__ out)
{
    const float4* srcs[4] = { w0, w1, w2, w3 };
    const int n4 = CDIM * CDIM / 4;
    const float4* src = srcs[blockIdx.y];
    float4* dst = out + (size_t)blockIdx.y * n4;
    int i = blockIdx.x * 256 + threadIdx.x;
    if (i < n4) {
        float4 v = src[i];
        v.x = rna(v.x); v.y = rna(v.y); v.z = rna(v.z); v.w = rna(v.w);
        dst[i] = v;
    }
}

// ---------------------------------------------------------------------------
// GEMM: C[b][m][n] = sum_k A[m][k]*B[k][n] (TB=0) / A[m][k]*B[n][k] (TB=1)
// CTA 128x128, 256 thr, 8 warps (2x4 of 64x32), BK=32, 2-stage cp.async.
// Stage: A [2 grp][128][16] (16KB) + B NN [2][16][136] / NT [2][128][16]
// (17408B) = 33792B. 2 stages = 67584B dynamic -> 2 CTAs/SM.
// ---------------------------------------------------------------------------
#define PBNN 136
#define STG_STRIDE 33792
#define GEMM_SMEM (2 * STG_STRIDE)

template<bool TB, bool BIAS, bool ROUND>
__global__ void __launch_bounds__(256, 2)
mma_gemm_kernel(const float* __restrict__ Ag, size_t sAs, int lda,
                const float* __restrict__ Bg, size_t sBs, int ldb,
                const float* __restrict__ bias,
                float* __restrict__ Cg, size_t sCs, int ldc, int K)
{
    extern __shared__ char smem[];
    const uint32_t sbase = smem_u32(smem);

    const int tid  = threadIdx.x;
    const int lane = tid & 31;
    const int wid  = tid >> 5;
    const int m0   = (wid & 1) * 64;
    const int n0   = (wid >> 1) * 32;
    const int row0 = blockIdx.y * 128;
    const int col0 = blockIdx.x * 128;

    const float* A = Ag + (size_t)blockIdx.z * sAs;
    const float* B = Bg + (size_t)blockIdx.z * sBs;
    float*       C = Cg + (size_t)blockIdx.z * sCs;

    float acc[4][4][4];
#pragma unroll
    for (int i = 0; i < 4; i++)
#pragma unroll
        for (int j = 0; j < 4; j++)
#pragma unroll
            for (int r = 0; r < 4; r++) acc[i][j][r] = 0.f;

    const int nch = K >> 5;

    auto load_stage = [&](int s, int k0) {
        const uint32_t baseA = sbase + (uint32_t)s * STG_STRIDE;
        const uint32_t baseB = baseA + 16384u;
#pragma unroll
        for (int i = 0; i < 4; i++) {           // A: 128 rows x 8 chunks
            const int c  = tid + i * 256;
            const int r  = c >> 3;
            const int cc = c & 7;
            const int g  = cc >> 2;
            const int q  = cc & 3;
            cp16(baseA + (uint32_t)(g * 2048 + r * 16 + q * 4) * 4,
                 A + (size_t)(row0 + r) * lda + k0 + cc * 4);
        }
        if (!TB) {
#pragma unroll
            for (int i = 0; i < 4; i++) {       // B NN: 32 k-rows x 32 chunks
                const int c  = tid + i * 256;
                const int j  = c >> 5;
                const int cc = c & 31;
                const int g  = j >> 4;
                const int jj = j & 15;
                const int pr = ((jj & 3) << 2) | (jj >> 2);
                cp16(baseB + (uint32_t)(g * 2176 + pr * PBNN + cc * 4) * 4,
                     B + (size_t)(k0 + j) * ldb + col0 + cc * 4);
            }
        } else {
#pragma unroll
            for (int i = 0; i < 4; i++) {       // B NT: 128 n-rows x 8 chunks
                const int c  = tid + i * 256;
                const int r  = c >> 3;
                const int cc = c & 7;
                const int g  = cc >> 2;
                const int q  = cc & 3;
                cp16(baseB + (uint32_t)(g * 2048 + r * 16 + q * 4) * 4,
                     B + (size_t)(col0 + r) * ldb + k0 + cc * 4);
            }
        }
        asm volatile("cp.async.commit_group;" ::: "memory");
    };

    load_stage(0, 0);

    const int lr = lane >> 2;
    const int lc = lane & 3;

    for (int ch = 0; ch < nch; ++ch) {
        const int s = ch & 1;
        if (ch + 1 < nch) {
            load_stage(s ^ 1, (ch + 1) << 5);
            asm volatile("cp.async.wait_group 1;" ::: "memory");
        } else {
            asm volatile("cp.async.wait_group 0;" ::: "memory");
        }
        __syncthreads();

        const float* sA = (const float*)(smem + (size_t)s * STG_STRIDE);
        const float* sB = (const float*)(smem + (size_t)s * STG_STRIDE + 16384);

#pragma unroll
        for (int g = 0; g < 2; g++) {
            const float* pAg = sA + g * 2048;
            float4 a0[4], a8[4];
#pragma unroll
            for (int mi = 0; mi < 4; mi++) {
                a0[mi] = *(const float4*)&pAg[(m0 + mi * 16 + lr)     * 16 + lc * 4];
                a8[mi] = *(const float4*)&pAg[(m0 + mi * 16 + lr + 8) * 16 + lc * 4];
            }
            float4 bf[4];
#pragma unroll
            for (int nj = 0; nj < 4; nj++) {
                if (TB) {
                    bf[nj] = *(const float4*)&sB[g * 2048 + (n0 + nj * 8 + lr) * 16 + lc * 4];
                } else {
                    const float* pBg = sB + g * 2176;
                    const int n = n0 + nj * 8 + lr;
                    bf[nj].x = pBg[(lc)      * PBNN + n];
                    bf[nj].y = pBg[(4 + lc)  * PBNN + n];
                    bf[nj].z = pBg[(8 + lc)  * PBNN + n];
                    bf[nj].w = pBg[(12 + lc) * PBNN + n];
                }
            }
#pragma unroll
            for (int nj = 0; nj < 4; nj++)
#pragma unroll
                for (int mi = 0; mi < 4; mi++) {
                    asm volatile(
                        "mma.sync.aligned.m16n8k8.row.col.f32.tf32.tf32.f32 "
                        "{%0,%1,%2,%3}, {%4,%5,%6,%7}, {%8,%9}, {%0,%1,%2,%3};"
                        : "+f"(acc[mi][nj][0]), "+f"(acc[mi][nj][1]),
                          "+f"(acc[mi][nj][2]), "+f"(acc[mi][nj][3])
                        : "r"(__float_as_uint(a0[mi].x)), "r"(__float_as_uint(a8[mi].x)),
                          "r"(__float_as_uint(a0[mi].y)), "r"(__float_as_uint(a8[mi].y)),
                          "r"(__float_as_uint(bf[nj].x)), "r"(__float_as_uint(bf[nj].y)));
                }
#pragma unroll
            for (int nj = 0; nj < 4; nj++)
#pragma unroll
                for (int mi = 0; mi < 4; mi++) {
                    asm volatile(
                        "mma.sync.aligned.m16n8k8.row.col.f32.tf32.tf32.f32 "
                        "{%0,%1,%2,%3}, {%4,%5,%6,%7}, {%8,%9}, {%0,%1,%2,%3};"
                        : "+f"(acc[mi][nj][0]), "+f"(acc[mi][nj][1]),
                          "+f"(acc[mi][nj][2]), "+f"(acc[mi][nj][3])
                        : "r"(__float_as_uint(a0[mi].z)), "r"(__float_as_uint(a8[mi].z)),
                          "r"(__float_as_uint(a0[mi].w)), "r"(__float_as_uint(a8[mi].w)),
                          "r"(__float_as_uint(bf[nj].z)), "r"(__float_as_uint(bf[nj].w)));
                }
        }
        __syncthreads();
    }

    // ---- epilogue ----
#pragma unroll
    for (int mi = 0; mi < 4; mi++) {
        const int r = row0 + m0 + mi * 16 + lr;
        const float bv0 = BIAS ? bias[r]     : 0.f;
        const float bv8 = BIAS ? bias[r + 8] : 0.f;
#pragma unroll
        for (int nj = 0; nj < 4; nj++) {
            const int c = col0 + n0 + nj * 8 + lc * 2;
            float2 v0 = { acc[mi][nj][0] + bv0, acc[mi][nj][1] + bv0 };
            float2 v1 = { acc[mi][nj][2] + bv8, acc[mi][nj][3] + bv8 };
            if (ROUND) {
                v0.x = rna(v0.x); v0.y = rna(v0.y);
                v1.x = rna(v1.x); v1.y = rna(v1.y);
            }
            *(float2*)(C + (size_t)r * ldc + c)       = v0;
            *(float2*)(C + (size_t)(r + 8) * ldc + c) = v1;
        }
    }
}

// ---------------------------------------------------------------------------
// Fused row softmax (rows of 1024) for two arrays, in place, tf32-rounded out.
// ---------------------------------------------------------------------------
__global__ __launch_bounds__(256)
void softmax_rows_kernel(float* __restrict__ d0, float* __restrict__ d1)
{
    float* data = blockIdx.y ? d1 : d0;
    float* row = data + (size_t)blockIdx.x * NDIM;
    const int tid = threadIdx.x;

    float4 v = *(const float4*)(row + tid * 4);

    float m = fmaxf(fmaxf(v.x, v.y), fmaxf(v.z, v.w));
#pragma unroll
    for (int off = 16; off > 0; off >>= 1)
        m = fmaxf(m, __shfl_xor_sync(0xffffffffu, m, off));
    __shared__ float smax[8];
    __shared__ float ssum[8];
    const int wid = tid >> 5, lid = tid & 31;
    if (lid == 0) smax[wid] = m;
    __syncthreads();
    if (wid == 0) {
        float tt = smax[lid & 7];
#pragma unroll
        for (int off = 4; off > 0; off >>= 1)
            tt = fmaxf(tt, __shfl_xor_sync(0xffffffffu, tt, off));
        if (lid == 0) smax[0] = tt;
    }
    __syncthreads();
    m = smax[0];

    v.x = __expf(v.x - m);
    v.y = __expf(v.y - m);
    v.z = __expf(v.z - m);
    v.w = __expf(v.w - m);
    float s = v.x + v.y + v.z + v.w;
#pragma unroll
    for (int off = 16; off > 0; off >>= 1)
        s += __shfl_xor_sync(0xffffffffu, s, off);
    if (lid == 0) ssum[wid] = s;
    __syncthreads();
    if (wid == 0) {
        float tt = ssum[lid & 7];
#pragma unroll
        for (int off = 4; off > 0; off >>= 1)
            tt += __shfl_xor_sync(0xffffffffu, tt, off);
        if (lid == 0) ssum[0] = tt;
    }
    __syncthreads();
    const float inv = 1.0f / ssum[0];

    v.x = rna(v.x * inv); v.y = rna(v.y * inv);
    v.z = rna(v.z * inv); v.w = rna(v.w * inv);
    *(float4*)(row + tid * 4) = v;
}

// ---------------------------------------------------------------------------
extern "C" void kernel_launch(void* const* d_in, const int* in_sizes, int n_in,
                              void* d_out, int out_size)
{
    const float* x  = (const float*)d_in[0];
    const float* wA = (const float*)d_in[1];
    const float* bA = (const float*)d_in[2];
    const float* wB = (const float*)d_in[3];
    const float* bB = (const float*)d_in[4];
    const float* wV = (const float*)d_in[5];
    const float* bV = (const float*)d_in[6];
    const float* wR = (const float*)d_in[7];
    const float* bR = (const float*)d_in[8];
    float* out = (float*)d_out;

    float *xr, *wr, *Am, *Bm, *Vm, *G, *G2;
    cudaGetSymbolAddress((void**)&xr, g_xr);
    cudaGetSymbolAddress((void**)&wr, g_w);
    cudaGetSymbolAddress((void**)&Am, g_A);
    cudaGetSymbolAddress((void**)&Bm, g_Bm);
    cudaGetSymbolAddress((void**)&Vm, g_Vm);
    cudaGetSymbolAddress((void**)&G,  g_G);
    cudaGetSymbolAddress((void**)&G2, g_G2);

    const float* wAr = wr;
    const float* wBr = wr + (size_t)CDIM * CDIM;
    const float* wVr = wr + (size_t)2 * CDIM * CDIM;
    const float* wRr = wr + (size_t)3 * CDIM * CDIM;

    const size_t sXN = (size_t)CDIM * NDIM;
    const size_t sCC = (size_t)CDIM * CDIM;

    cudaFuncSetAttribute(mma_gemm_kernel<false, true,  true >, cudaFuncAttributeMaxDynamicSharedMemorySize, GEMM_SMEM);
    cudaFuncSetAttribute(mma_gemm_kernel<false, true,  false>, cudaFuncAttributeMaxDynamicSharedMemorySize, GEMM_SMEM);
    cudaFuncSetAttribute(mma_gemm_kernel<true,  false, true >, cudaFuncAttributeMaxDynamicSharedMemorySize, GEMM_SMEM);
    cudaFuncSetAttribute(mma_gemm_kernel<false, false, true >, cudaFuncAttributeMaxDynamicSharedMemorySize, GEMM_SMEM);

    dim3 blk(256);

    // 0) pre-round x and weights to tf32
    {
        const int n4x = (int)(BSZ * sXN / 4);
        preround_kernel<<<(n4x + 255) / 256, blk>>>((const float4*)x, (float4*)xr, n4x);
        const int n4w = CDIM * CDIM / 4;
        dim3 gw((n4w + 255) / 256, 4);
        preround_w_kernel<<<gw, blk>>>((const float4*)wA, (const float4*)wB,
                                       (const float4*)wV, (const float4*)wR,
                                       (float4*)wr);
    }

    // 1) Projections (NN): M=512, N=1024, K=512
    {
        dim3 g(NDIM / 128, CDIM / 128, BSZ);
        mma_gemm_kernel<false, true,  true ><<<g, blk, GEMM_SMEM>>>(wAr, 0, CDIM, xr, sXN, NDIM, bA, Am, sXN, NDIM, CDIM);
        mma_gemm_kernel<false, true,  false><<<g, blk, GEMM_SMEM>>>(wBr, 0, CDIM, xr, sXN, NDIM, bB, Bm, sXN, NDIM, CDIM);
        mma_gemm_kernel<false, true,  false><<<g, blk, GEMM_SMEM>>>(wVr, 0, CDIM, xr, sXN, NDIM, bV, Vm, sXN, NDIM, CDIM);
    }

    // 2) softmax over spatial dim
    {
        dim3 g(BSZ * CDIM, 2);
        softmax_rows_kernel<<<g, blk>>>(Bm, Vm);
    }

    // 3) G = Am @ Bm^T (NT), M=N=512, K=1024
    {
        dim3 g(CDIM / 128, CDIM / 128, BSZ);
        mma_gemm_kernel<true, false, true><<<g, blk, GEMM_SMEM>>>(Am, sXN, NDIM, Bm, sXN, NDIM, nullptr, G, sCC, CDIM, NDIM);
    }

    // 4) G2 = wR @ G (NN), M=N=K=512
    {
        dim3 g(CDIM / 128, CDIM / 128, BSZ);
        mma_gemm_kernel<false, false, true><<<g, blk, GEMM_SMEM>>>(wRr, 0, CDIM, G, sCC, CDIM, nullptr, G2, sCC, CDIM, CDIM);
    }

    // 5) out = G2 @ Vm + bR (NN), M=512, N=1024, K=512
    {
        dim3 g(NDIM / 128, CDIM / 128, BSZ);
        mma_gemm_kernel<false, true, false><<<g, blk, GEMM_SMEM>>>(G2, sCC, CDIM, Vm, sXN, NDIM, bR, out, sXN, NDIM, CDIM);
    }
}

// round 11
// speedup vs baseline: 1.1639x; 1.0134x over previous
#include <cuda_runtime.h>
#include <cstdint>

// ---------------------------------------------------------------------------
// DoubleAttention via mma.sync tf32, R7.
// vs R6: 3 projection GEMMs fused into ONE launch (M=1536 stacked weights)
// writing contiguous P=[B][1536][1024] (rows 0-511=A, 512-1023=Bm,
// 1024-1535=Vm per batch). Saves 2 launch tails and improves L2 reuse of x.
// Inner GEMM loop unchanged from R6 (proven 2 CTAs/SM config).
// ---------------------------------------------------------------------------

#define BSZ   32
#define CDIM  512
#define NDIM  1024
#define MSTK  1536
#define PSTRIDE ((size_t)MSTK * NDIM)

__device__ float g_xr  [(size_t)BSZ * CDIM * NDIM];
__device__ float g_w   [4][(size_t)CDIM * CDIM];
__device__ float g_bias[MSTK];
__device__ float g_P   [(size_t)BSZ * MSTK * NDIM];
__device__ float g_G   [(size_t)BSZ * CDIM * CDIM];
__device__ float g_G2  [(size_t)BSZ * CDIM * CDIM];

__device__ __forceinline__ uint32_t smem_u32(const void* p) {
    uint32_t a;
    asm("{ .reg .u64 t; cvta.to.shared.u64 t, %1; cvt.u32.u64 %0, t; }"
        : "=r"(a) : "l"(p));
    return a;
}
__device__ __forceinline__ void cp16(uint32_t dst, const void* src) {
    asm volatile("cp.async.cg.shared.global [%0], [%1], 16;"
                 :: "r"(dst), "l"(src));
}
__device__ __forceinline__ float rna(float x) {
    float y;
    asm("cvt.rna.tf32.f32 %0, %1;" : "=f"(y) : "f"(x));
    return y;
}

// ---------------------------------------------------------------------------
__global__ __launch_bounds__(256)
void preround_kernel(const float4* __restrict__ in, float4* __restrict__ out, int n4)
{
    int i = blockIdx.x * 256 + threadIdx.x;
    if (i < n4) {
        float4 v = in[i];
        v.x = rna(v.x); v.y = rna(v.y); v.z = rna(v.z); v.w = rna(v.w);
        out[i] = v;
    }
}

// y<4: round weight y into g_w[y]; y==4: stack biases into g_bias.
__global__ __launch_bounds__(256)
void preround_w_kernel(const float4* w0, const float4* w1,
                       const float4* w2, const float4* w3,
                       const float* b0, const float* b1, const float* b2,
                       float4* __restrict__ outw, float* __restrict__ outb)
{
    const int y = blockIdx.y;
    const int i = blockIdx.x * 256 + threadIdx.x;
    if (y < 4) {
        const float4* srcs[4] = { w0, w1, w2, w3 };
        const int n4 = CDIM * CDIM / 4;
        if (i < n4) {
            float4 v = srcs[y][i];
            v.x = rna(v.x); v.y = rna(v.y); v.z = rna(v.z); v.w = rna(v.w);
            outw[(size_t)y * n4 + i] = v;
        }
    } else {
        if (i < MSTK) {
            float v = (i < 512) ? b0[i] : (i < 1024) ? b1[i - 512] : b2[i - 1024];
            outb[i] = v;
        }
    }
}

// ---------------------------------------------------------------------------
#define PBNN 136
#define STG_STRIDE 33792
#define GEMM_SMEM (2 * STG_STRIDE)

template<bool TB, bool BIAS, bool ROUND>
__global__ void __launch_bounds__(256, 2)
mma_gemm_kernel(const float* __restrict__ Ag, size_t sAs, int lda,
                const float* __restrict__ Bg, size_t sBs, int ldb,
                const float* __restrict__ bias,
                float* __restrict__ Cg, size_t sCs, int ldc, int K)
{
    extern __shared__ char smem[];
    const uint32_t sbase = smem_u32(smem);

    const int tid  = threadIdx.x;
    const int lane = tid & 31;
    const int wid  = tid >> 5;
    const int m0   = (wid & 1) * 64;
    const int n0   = (wid >> 1) * 32;
    const int row0 = blockIdx.y * 128;
    const int col0 = blockIdx.x * 128;

    const float* A = Ag + (size_t)blockIdx.z * sAs;
    const float* B = Bg + (size_t)blockIdx.z * sBs;
    float*       C = Cg + (size_t)blockIdx.z * sCs;

    float acc[4][4][4];
#pragma unroll
    for (int i = 0; i < 4; i++)
#pragma unroll
        for (int j = 0; j < 4; j++)
#pragma unroll
            for (int r = 0; r < 4; r++) acc[i][j][r] = 0.f;

    const int nch = K >> 5;

    auto load_stage = [&](int s, int k0) {
        const uint32_t baseA = sbase + (uint32_t)s * STG_STRIDE;
        const uint32_t baseB = baseA + 16384u;
#pragma unroll
        for (int i = 0; i < 4; i++) {
            const int c  = tid + i * 256;
            const int r  = c >> 3;
            const int cc = c & 7;
            const int g  = cc >> 2;
            const int q  = cc & 3;
            cp16(baseA + (uint32_t)(g * 2048 + r * 16 + q * 4) * 4,
                 A + (size_t)(row0 + r) * lda + k0 + cc * 4);
        }
        if (!TB) {
#pragma unroll
            for (int i = 0; i < 4; i++) {
                const int c  = tid + i * 256;
                const int j  = c >> 5;
                const int cc = c & 31;
                const int g  = j >> 4;
                const int jj = j & 15;
                const int pr = ((jj & 3) << 2) | (jj >> 2);
                cp16(baseB + (uint32_t)(g * 2176 + pr * PBNN + cc * 4) * 4,
                     B + (size_t)(k0 + j) * ldb + col0 + cc * 4);
            }
        } else {
#pragma unroll
            for (int i = 0; i < 4; i++) {
                const int c  = tid + i * 256;
                const int r  = c >> 3;
                const int cc = c & 7;
                const int g  = cc >> 2;
                const int q  = cc & 3;
                cp16(baseB + (uint32_t)(g * 2048 + r * 16 + q * 4) * 4,
                     B + (size_t)(col0 + r) * ldb + k0 + cc * 4);
            }
        }
        asm volatile("cp.async.commit_group;" ::: "memory");
    };

    load_stage(0, 0);

    const int lr = lane >> 2;
    const int lc = lane & 3;

    for (int ch = 0; ch < nch; ++ch) {
        const int s = ch & 1;
        if (ch + 1 < nch) {
            load_stage(s ^ 1, (ch + 1) << 5);
            asm volatile("cp.async.wait_group 1;" ::: "memory");
        } else {
            asm volatile("cp.async.wait_group 0;" ::: "memory");
        }
        __syncthreads();

        const float* sA = (const float*)(smem + (size_t)s * STG_STRIDE);
        const float* sB = (const float*)(smem + (size_t)s * STG_STRIDE + 16384);

#pragma unroll
        for (int g = 0; g < 2; g++) {
            const float* pAg = sA + g * 2048;
            float4 a0[4], a8[4];
#pragma unroll
            for (int mi = 0; mi < 4; mi++) {
                a0[mi] = *(const float4*)&pAg[(m0 + mi * 16 + lr)     * 16 + lc * 4];
                a8[mi] = *(const float4*)&pAg[(m0 + mi * 16 + lr + 8) * 16 + lc * 4];
            }
            float4 bf[4];
#pragma unroll
            for (int nj = 0; nj < 4; nj++) {
                if (TB) {
                    bf[nj] = *(const float4*)&sB[g * 2048 + (n0 + nj * 8 + lr) * 16 + lc * 4];
                } else {
                    const float* pBg = sB + g * 2176;
                    const int n = n0 + nj * 8 + lr;
                    bf[nj].x = pBg[(lc)      * PBNN + n];
                    bf[nj].y = pBg[(4 + lc)  * PBNN + n];
                    bf[nj].z = pBg[(8 + lc)  * PBNN + n];
                    bf[nj].w = pBg[(12 + lc) * PBNN + n];
                }
            }
#pragma unroll
            for (int nj = 0; nj < 4; nj++)
#pragma unroll
                for (int mi = 0; mi < 4; mi++) {
                    asm volatile(
                        "mma.sync.aligned.m16n8k8.row.col.f32.tf32.tf32.f32 "
                        "{%0,%1,%2,%3}, {%4,%5,%6,%7}, {%8,%9}, {%0,%1,%2,%3};"
                        : "+f"(acc[mi][nj][0]), "+f"(acc[mi][nj][1]),
                          "+f"(acc[mi][nj][2]), "+f"(acc[mi][nj][3])
                        : "r"(__float_as_uint(a0[mi].x)), "r"(__float_as_uint(a8[mi].x)),
                          "r"(__float_as_uint(a0[mi].y)), "r"(__float_as_uint(a8[mi].y)),
                          "r"(__float_as_uint(bf[nj].x)), "r"(__float_as_uint(bf[nj].y)));
                }
#pragma unroll
            for (int nj = 0; nj < 4; nj++)
#pragma unroll
                for (int mi = 0; mi < 4; mi++) {
                    asm volatile(
                        "mma.sync.aligned.m16n8k8.row.col.f32.tf32.tf32.f32 "
                        "{%0,%1,%2,%3}, {%4,%5,%6,%7}, {%8,%9}, {%0,%1,%2,%3};"
                        : "+f"(acc[mi][nj][0]), "+f"(acc[mi][nj][1]),
                          "+f"(acc[mi][nj][2]), "+f"(acc[mi][nj][3])
                        : "r"(__float_as_uint(a0[mi].z)), "r"(__float_as_uint(a8[mi].z)),
                          "r"(__float_as_uint(a0[mi].w)), "r"(__float_as_uint(a8[mi].w)),
                          "r"(__float_as_uint(bf[nj].z)), "r"(__float_as_uint(bf[nj].w)));
                }
        }
        __syncthreads();
    }

#pragma unroll
    for (int mi = 0; mi < 4; mi++) {
        const int r = row0 + m0 + mi * 16 + lr;
        const float bv0 = BIAS ? bias[r]     : 0.f;
        const float bv8 = BIAS ? bias[r + 8] : 0.f;
#pragma unroll
        for (int nj = 0; nj < 4; nj++) {
            const int c = col0 + n0 + nj * 8 + lc * 2;
            float2 v0 = { acc[mi][nj][0] + bv0, acc[mi][nj][1] + bv0 };
            float2 v1 = { acc[mi][nj][2] + bv8, acc[mi][nj][3] + bv8 };
            if (ROUND) {
                v0.x = rna(v0.x); v0.y = rna(v0.y);
                v1.x = rna(v1.x); v1.y = rna(v1.y);
            }
            *(float2*)(C + (size_t)r * ldc + c)       = v0;
            *(float2*)(C + (size_t)(r + 8) * ldc + c) = v1;
        }
    }
}

// ---------------------------------------------------------------------------
// Row softmax inside strided P. blockIdx.y: 0->Bm (offset 512 rows),
// 1->Vm (offset 1024 rows). blockIdx.x = batch*512 + row.
// ---------------------------------------------------------------------------
__global__ __launch_bounds__(256)
void softmax_rows_kernel(float* __restrict__ P)
{
    const int gr    = blockIdx.x;
    const int batch = gr >> 9;
    const int rin   = gr & 511;
    float* row = P + (size_t)batch * PSTRIDE
                   + (size_t)(512 + (blockIdx.y << 9) + rin) * NDIM;
    const int tid = threadIdx.x;

    float4 v = *(const float4*)(row + tid * 4);

    float m = fmaxf(fmaxf(v.x, v.y), fmaxf(v.z, v.w));
#pragma unroll
    for (int o = 16; o > 0; o >>= 1)
        m = fmaxf(m, __shfl_xor_sync(0xffffffffu, m, o));
    __shared__ float smax[8];
    __shared__ float ssum[8];
    const int wid = tid >> 5, lid = tid & 31;
    if (lid == 0) smax[wid] = m;
    __syncthreads();
    if (wid == 0) {
        float tt = smax[lid & 7];
#pragma unroll
        for (int o = 4; o > 0; o >>= 1)
            tt = fmaxf(tt, __shfl_xor_sync(0xffffffffu, tt, o));
        if (lid == 0) smax[0] = tt;
    }
    __syncthreads();
    m = smax[0];

    v.x = __expf(v.x - m);
    v.y = __expf(v.y - m);
    v.z = __expf(v.z - m);
    v.w = __expf(v.w - m);
    float s = v.x + v.y + v.z + v.w;
#pragma unroll
    for (int o = 16; o > 0; o >>= 1)
        s += __shfl_xor_sync(0xffffffffu, s, o);
    if (lid == 0) ssum[wid] = s;
    __syncthreads();
    if (wid == 0) {
        float tt = ssum[lid & 7];
#pragma unroll
        for (int o = 4; o > 0; o >>= 1)
            tt += __shfl_xor_sync(0xffffffffu, tt, o);
        if (lid == 0) ssum[0] = tt;
    }
    __syncthreads();
    const float inv = 1.0f / ssum[0];

    v.x = rna(v.x * inv); v.y = rna(v.y * inv);
    v.z = rna(v.z * inv); v.w = rna(v.w * inv);
    *(float4*)(row + tid * 4) = v;
}

// ---------------------------------------------------------------------------
extern "C" void kernel_launch(void* const* d_in, const int* in_sizes, int n_in,
                              void* d_out, int out_size)
{
    const float* x  = (const float*)d_in[0];
    const float* wA = (const float*)d_in[1];
    const float* bA = (const float*)d_in[2];
    const float* wB = (const float*)d_in[3];
    const float* bB = (const float*)d_in[4];
    const float* wV = (const float*)d_in[5];
    const float* bV = (const float*)d_in[6];
    const float* wR = (const float*)d_in[7];
    const float* bR = (const float*)d_in[8];
    float* out = (float*)d_out;

    float *xr, *wr, *bias, *P, *G, *G2;
    cudaGetSymbolAddress((void**)&xr,   g_xr);
    cudaGetSymbolAddress((void**)&wr,   g_w);
    cudaGetSymbolAddress((void**)&bias, g_bias);
    cudaGetSymbolAddress((void**)&P,    g_P);
    cudaGetSymbolAddress((void**)&G,    g_G);
    cudaGetSymbolAddress((void**)&G2,   g_G2);

    const float* wRr = wr + (size_t)3 * CDIM * CDIM;
    const float* Am  = P;
    const float* Bm  = P + (size_t)512 * NDIM;
    const float* Vm  = P + (size_t)1024 * NDIM;

    const size_t sXN = (size_t)CDIM * NDIM;
    const size_t sCC = (size_t)CDIM * CDIM;

    cudaFuncSetAttribute(mma_gemm_kernel<false, true,  true >, cudaFuncAttributeMaxDynamicSharedMemorySize, GEMM_SMEM);
    cudaFuncSetAttribute(mma_gemm_kernel<true,  false, true >, cudaFuncAttributeMaxDynamicSharedMemorySize, GEMM_SMEM);
    cudaFuncSetAttribute(mma_gemm_kernel<false, false, true >, cudaFuncAttributeMaxDynamicSharedMemorySize, GEMM_SMEM);
    cudaFuncSetAttribute(mma_gemm_kernel<false, true,  false>, cudaFuncAttributeMaxDynamicSharedMemorySize, GEMM_SMEM);

    dim3 blk(256);

    // 0) pre-round x; round+stack weights, stack biases
    {
        const int n4x = (int)(BSZ * sXN / 4);
        preround_kernel<<<(n4x + 255) / 256, blk>>>((const float4*)x, (float4*)xr, n4x);
        const int n4w = CDIM * CDIM / 4;
        dim3 gw((n4w + 255) / 256, 5);
        preround_w_kernel<<<gw, blk>>>((const float4*)wA, (const float4*)wB,
                                       (const float4*)wV, (const float4*)wR,
                                       bA, bB, bV,
                                       (float4*)wr, bias);
    }

    // 1) Fused projections (NN): M=1536 (A|Bm|Vm), N=1024, K=512, rounded
    {
        dim3 g(NDIM / 128, MSTK / 128, BSZ);
        mma_gemm_kernel<false, true, true><<<g, blk, GEMM_SMEM>>>(
            wr, 0, CDIM, xr, sXN, NDIM, bias, P, PSTRIDE, NDIM, CDIM);
    }

    // 2) softmax over spatial dim (Bm, Vm row-blocks of P)
    {
        dim3 g(BSZ * CDIM, 2);
        softmax_rows_kernel<<<g, blk>>>(P);
    }

    // 3) G = Am @ Bm^T (NT), M=N=512, K=1024, rounded
    {
        dim3 g(CDIM / 128, CDIM / 128, BSZ);
        mma_gemm_kernel<true, false, true><<<g, blk, GEMM_SMEM>>>(
            Am, PSTRIDE, NDIM, Bm, PSTRIDE, NDIM, nullptr, G, sCC, CDIM, NDIM);
    }

    // 4) G2 = wR @ G (NN), M=N=K=512, rounded
    {
        dim3 g(CDIM / 128, CDIM / 128, BSZ);
        mma_gemm_kernel<false, false, true><<<g, blk, GEMM_SMEM>>>(
            wRr, 0, CDIM, G, sCC, CDIM, nullptr, G2, sCC, CDIM, CDIM);
    }

    // 5) out = G2 @ Vm + bR (NN), M=512, N=1024, K=512 (out stride 512*1024)
    {
        dim3 g(NDIM / 128, CDIM / 128, BSZ);
        mma_gemm_kernel<false, true, false><<<g, blk, GEMM_SMEM>>>(
            G2, sCC, CDIM, Vm, PSTRIDE, NDIM, bR, out, sXN, NDIM, CDIM);
    }
}

// round 12
// speedup vs baseline: 2.4321x; 2.0895x over previous
#include <cuda_runtime.h>
#include <cuda_fp16.h>
#include <cstdint>

// ---------------------------------------------------------------------------
// DoubleAttention, R8: fp16 tensor cores (mma.m16n8k16, fp32 accum).
// fp16 mantissa (11 bit) == tf32 mantissa -> same rounding error as the
// tf32 path, at 2x tensor rate, half the HMMA count, half the traffic.
// All GEMMs NT (both operands K-major half, ldmatrix fragments):
//   xh  = transpose(x)->half        [B][1024 n][512 c]
//   P   = Wh (.) xh^T + bias        [B][1536][1024] half  (A|Bm|Vm)
//   softmax rows of Bm,Vm (half in/out, fp32 math)
//   VmT = transpose(Vm)             [B][1024][512] half
//   GT  = Bm (.) Am^T               [B][512 d][512 c] half
//   G2  = wRh (.) GT^T              [B][512 o][512 d] half
//   out = G2 (.) VmT^T + bR         [B][512][1024] float
// ---------------------------------------------------------------------------

#define BSZ   32
#define CDIM  512
#define NDIM  1024
#define MSTK  1536
#define PSTRIDE ((size_t)MSTK * NDIM)

__device__ __half g_xh [(size_t)BSZ * NDIM * CDIM];
__device__ __half g_wh [(size_t)2048 * CDIM];          // wA|wB|wV|wR rows
__device__ float  g_bias[MSTK];
__device__ __half g_P  [(size_t)BSZ * MSTK * NDIM];
__device__ __half g_VmT[(size_t)BSZ * NDIM * CDIM];
__device__ __half g_GT [(size_t)BSZ * CDIM * CDIM];
__device__ __half g_G2 [(size_t)BSZ * CDIM * CDIM];

__device__ __forceinline__ uint32_t smem_u32(const void* p) {
    uint32_t a;
    asm("{ .reg .u64 t; cvta.to.shared.u64 t, %1; cvt.u32.u64 %0, t; }"
        : "=r"(a) : "l"(p));
    return a;
}
__device__ __forceinline__ void cp16(uint32_t dst, const void* src) {
    asm volatile("cp.async.cg.shared.global [%0], [%1], 16;"
                 :: "r"(dst), "l"(src));
}

#define LDSM4(r, a) \
    asm volatile("ldmatrix.sync.aligned.m8n8.x4.shared.b16 {%0,%1,%2,%3}, [%4];" \
                 : "=r"((r)[0]), "=r"((r)[1]), "=r"((r)[2]), "=r"((r)[3]) : "r"(a))

#define HMMA(c, a, b0v, b1v) \
    asm volatile("mma.sync.aligned.m16n8k16.row.col.f32.f16.f16.f32 " \
                 "{%0,%1,%2,%3}, {%4,%5,%6,%7}, {%8,%9}, {%0,%1,%2,%3};" \
                 : "+f"((c)[0]), "+f"((c)[1]), "+f"((c)[2]), "+f"((c)[3]) \
                 : "r"((a)[0]), "r"((a)[1]), "r"((a)[2]), "r"((a)[3]), \
                   "r"(b0v), "r"(b1v))

// ---------------------------------------------------------------------------
// Conversions / transposes
// ---------------------------------------------------------------------------
// x [B][512 c][1024 n] f32 -> xh [B][1024 n][512 c] half
__global__ __launch_bounds__(256)
void tconv_x_kernel(const float* __restrict__ x, __half* __restrict__ xh)
{
    __shared__ float t[32][33];
    const int tx = threadIdx.x, ty = threadIdx.y;
    const int n0 = blockIdx.x * 32, c0 = blockIdx.y * 32;
    const float* in = x + (size_t)blockIdx.z * CDIM * NDIM;
    __half* out = xh + (size_t)blockIdx.z * NDIM * CDIM;
#pragma unroll
    for (int i = 0; i < 4; i++)
        t[ty + i * 8][tx] = in[(size_t)(c0 + ty + i * 8) * NDIM + n0 + tx];
    __syncthreads();
#pragma unroll
    for (int i = 0; i < 4; i++)
        out[(size_t)(n0 + ty + i * 8) * CDIM + c0 + tx] =
            __float2half_rn(t[tx][ty + i * 8]);
}

// Vm rows of P (half [512 d][1024 n]) -> VmT [1024 n][512 d] half
__global__ __launch_bounds__(256)
void tconv_v_kernel(const __half* __restrict__ P, __half* __restrict__ VmT)
{
    __shared__ __half t[32][33];
    const int tx = threadIdx.x, ty = threadIdx.y;
    const int n0 = blockIdx.x * 32, d0 = blockIdx.y * 32;
    const __half* in = P + (size_t)blockIdx.z * PSTRIDE + (size_t)1024 * NDIM;
    __half* out = VmT + (size_t)blockIdx.z * NDIM * CDIM;
#pragma unroll
    for (int i = 0; i < 4; i++)
        t[ty + i * 8][tx] = in[(size_t)(d0 + ty + i * 8) * NDIM + n0 + tx];
    __syncthreads();
#pragma unroll
    for (int i = 0; i < 4; i++)
        out[(size_t)(n0 + ty + i * 8) * CDIM + d0 + tx] = t[tx][ty + i * 8];
}

// y<4: convert weight y into wh row-block y; y==4: stack biases (float).
__global__ __launch_bounds__(256)
void wconv_kernel(const float* w0, const float* w1,
                  const float* w2, const float* w3,
                  const float* b0, const float* b1, const float* b2,
                  __half* __restrict__ wh, float* __restrict__ bias)
{
    const int y = blockIdx.y;
    const int i = blockIdx.x * 256 + threadIdx.x;
    if (y < 4) {
        const float* srcs[4] = { w0, w1, w2, w3 };
        if (i < CDIM * CDIM)
            wh[(size_t)y * CDIM * CDIM + i] = __float2half_rn(srcs[y][i]);
    } else {
        if (i < MSTK) {
            float v = (i < 512) ? b0[i] : (i < 1024) ? b1[i - 512] : b2[i - 1024];
            bias[i] = v;
        }
    }
}

// ---------------------------------------------------------------------------
// fp16 NT GEMM: C[b][m][n] = sum_k A[b][m][k] * B[b][n][k]  (+ bias[m])
// A,B half K-major. CTA 128x128, 256 thr, 8 warps (2x4 of 64x32), BK=64,
// 2-stage cp.async (32KB/stage -> 64KB, 2 CTAs/SM). ldmatrix fragments.
// SMEM layout per operand: 128 rows x 128B, 16B chunk swizzle cc^(r&7).
// ---------------------------------------------------------------------------
#define HSTG 32768
#define HGEMM_SMEM (2 * HSTG)

template<bool BIAS, bool OUTF>
__global__ void __launch_bounds__(256, 2)
hgemm_nt_kernel(const __half* __restrict__ Ag, size_t sAs, int lda,
                const __half* __restrict__ Bg, size_t sBs, int ldb,
                const float* __restrict__ bias,
                void* __restrict__ Cg, size_t sCs, int ldc, int K)
{
    extern __shared__ char smem[];
    const uint32_t sbase = smem_u32(smem);

    const int tid  = threadIdx.x;
    const int lane = tid & 31;
    const int wid  = tid >> 5;
    const int m0   = (wid & 1) * 64;
    const int n0   = (wid >> 1) * 32;
    const int row0 = blockIdx.y * 128;
    const int col0 = blockIdx.x * 128;

    const __half* A = Ag + (size_t)blockIdx.z * sAs;
    const __half* B = Bg + (size_t)blockIdx.z * sBs;

    float acc[4][4][4];
#pragma unroll
    for (int i = 0; i < 4; i++)
#pragma unroll
        for (int j = 0; j < 4; j++)
#pragma unroll
            for (int r = 0; r < 4; r++) acc[i][j][r] = 0.f;

    const int nch = K >> 6;           // BK = 64 halves = 128B rows

    auto load_stage = [&](int s, int k0) {
        const uint32_t bA = sbase + (uint32_t)s * HSTG;
        const uint32_t bB = bA + 16384u;
#pragma unroll
        for (int i = 0; i < 4; i++) {         // 1024 chunks per operand
            const int idx = tid + i * 256;
            const int r  = idx >> 3;          // 0..127
            const int cc = idx & 7;           // 16B chunk in row
            const int sw = cc ^ (r & 7);
            cp16(bA + (uint32_t)(r * 128 + sw * 16),
                 A + (size_t)(row0 + r) * lda + k0 + cc * 8);
            cp16(bB + (uint32_t)(r * 128 + sw * 16),
                 B + (size_t)(col0 + r) * ldb + k0 + cc * 8);
        }
        asm volatile("cp.async.commit_group;" ::: "memory");
    };

    load_stage(0, 0);

    // lane-constant address pieces
    const int l7  = lane & 7;
    const uint32_t aRowOff = (uint32_t)(m0 + (lane & 15)) * 128;
    const int aHi = lane >> 4;                 // chunk parity for A
    const uint32_t bRowOff = (uint32_t)(n0 + l7 + ((lane >> 4) << 3)) * 128;
    const int bHi = (lane >> 3) & 1;           // chunk parity for B

    for (int ch = 0; ch < nch; ++ch) {
        const int s = ch & 1;
        if (ch + 1 < nch) {
            load_stage(s ^ 1, (ch + 1) << 6);
            asm volatile("cp.async.wait_group 1;" ::: "memory");
        } else {
            asm volatile("cp.async.wait_group 0;" ::: "memory");
        }
        __syncthreads();

        const uint32_t stA = sbase + (uint32_t)s * HSTG;
        const uint32_t stB = stA + 16384u;

#pragma unroll
        for (int ks = 0; ks < 4; ks++) {
            const uint32_t swA = (uint32_t)(((2 * ks + aHi) ^ l7) * 16);
            const uint32_t swB = (uint32_t)(((2 * ks + bHi) ^ l7) * 16);

            uint32_t aF[4][4];
#pragma unroll
            for (int mi = 0; mi < 4; mi++)
                LDSM4(aF[mi], stA + aRowOff + mi * 2048 + swA);

            uint32_t bF[4][2];
            {
                uint32_t t0[4], t1[4];
                LDSM4(t0, stB + bRowOff + swB);          // nj 0,1
                LDSM4(t1, stB + bRowOff + 2048 + swB);   // nj 2,3
                bF[0][0] = t0[0]; bF[0][1] = t0[1];
                bF[1][0] = t0[2]; bF[1][1] = t0[3];
                bF[2][0] = t1[0]; bF[2][1] = t1[1];
                bF[3][0] = t1[2]; bF[3][1] = t1[3];
            }
#pragma unroll
            for (int nj = 0; nj < 4; nj++)
#pragma unroll
                for (int mi = 0; mi < 4; mi++)
                    HMMA(acc[mi][nj], aF[mi], bF[nj][0], bF[nj][1]);
        }
        __syncthreads();
    }

    // ---- epilogue ----
    const int lr = lane >> 2;
    const int lc = lane & 3;
#pragma unroll
    for (int mi = 0; mi < 4; mi++) {
        const int r = row0 + m0 + mi * 16 + lr;
        const float bv0 = BIAS ? bias[r]     : 0.f;
        const float bv8 = BIAS ? bias[r + 8] : 0.f;
#pragma unroll
        for (int nj = 0; nj < 4; nj++) {
            const int c = col0 + n0 + nj * 8 + lc * 2;
            const float v00 = acc[mi][nj][0] + bv0;
            const float v01 = acc[mi][nj][1] + bv0;
            const float v80 = acc[mi][nj][2] + bv8;
            const float v81 = acc[mi][nj][3] + bv8;
            if (OUTF) {
                float* C = (float*)Cg + (size_t)blockIdx.z * sCs;
                *(float2*)(C + (size_t)r * ldc + c)       = make_float2(v00, v01);
                *(float2*)(C + (size_t)(r + 8) * ldc + c) = make_float2(v80, v81);
            } else {
                __half* C = (__half*)Cg + (size_t)blockIdx.z * sCs;
                *(__half2*)(C + (size_t)r * ldc + c)       = __floats2half2_rn(v00, v01);
                *(__half2*)(C + (size_t)(r + 8) * ldc + c) = __floats2half2_rn(v80, v81);
            }
        }
    }
}

// ---------------------------------------------------------------------------
// Row softmax on half rows of P (1024 halves), fp32 math, half output.
// blockIdx.y: 0 -> Bm block (rows 512+), 1 -> Vm block (rows 1024+).
// ---------------------------------------------------------------------------
__global__ __launch_bounds__(256)
void softmax_rows_kernel(__half* __restrict__ P)
{
    const int gr    = blockIdx.x;
    const int batch = gr >> 9;
    const int rin   = gr & 511;
    __half* row = P + (size_t)batch * PSTRIDE
                    + (size_t)(512 + (blockIdx.y << 9) + rin) * NDIM;
    const int tid = threadIdx.x;

    __half2* hp = (__half2*)row + tid * 2;
    float2 f0 = __half22float2(hp[0]);
    float2 f1 = __half22float2(hp[1]);

    float m = fmaxf(fmaxf(f0.x, f0.y), fmaxf(f1.x, f1.y));
#pragma unroll
    for (int o = 16; o > 0; o >>= 1)
        m = fmaxf(m, __shfl_xor_sync(0xffffffffu, m, o));
    __shared__ float smax[8];
    __shared__ float ssum[8];
    const int wid = tid >> 5, lid = tid & 31;
    if (lid == 0) smax[wid] = m;
    __syncthreads();
    if (wid == 0) {
        float tt = smax[lid & 7];
#pragma unroll
        for (int o = 4; o > 0; o >>= 1)
            tt = fmaxf(tt, __shfl_xor_sync(0xffffffffu, tt, o));
        if (lid == 0) smax[0] = tt;
    }
    __syncthreads();
    m = smax[0];

    f0.x = __expf(f0.x - m); f0.y = __expf(f0.y - m);
    f1.x = __expf(f1.x - m); f1.y = __expf(f1.y - m);
    float s = f0.x + f0.y + f1.x + f1.y;
#pragma unroll
    for (int o = 16; o > 0; o >>= 1)
        s += __shfl_xor_sync(0xffffffffu, s, o);
    if (lid == 0) ssum[wid] = s;
    __syncthreads();
    if (wid == 0) {
        float tt = ssum[lid & 7];
#pragma unroll
        for (int o = 4; o > 0; o >>= 1)
            tt += __shfl_xor_sync(0xffffffffu, tt, o);
        if (lid == 0) ssum[0] = tt;
    }
    __syncthreads();
    const float inv = 1.0f / ssum[0];

    hp[0] = __floats2half2_rn(f0.x * inv, f0.y * inv);
    hp[1] = __floats2half2_rn(f1.x * inv, f1.y * inv);
}

// ---------------------------------------------------------------------------
extern "C" void kernel_launch(void* const* d_in, const int* in_sizes, int n_in,
                              void* d_out, int out_size)
{
    const float* x  = (const float*)d_in[0];
    const float* wA = (const float*)d_in[1];
    const float* bA = (const float*)d_in[2];
    const float* wB = (const float*)d_in[3];
    const float* bB = (const float*)d_in[4];
    const float* wV = (const float*)d_in[5];
    const float* bV = (const float*)d_in[6];
    const float* wR = (const float*)d_in[7];
    const float* bR = (const float*)d_in[8];
    float* out = (float*)d_out;

    __half *xh, *wh, *P, *VmT, *GT, *G2;
    float *bias;
    cudaGetSymbolAddress((void**)&xh,   g_xh);
    cudaGetSymbolAddress((void**)&wh,   g_wh);
    cudaGetSymbolAddress((void**)&bias, g_bias);
    cudaGetSymbolAddress((void**)&P,    g_P);
    cudaGetSymbolAddress((void**)&VmT,  g_VmT);
    cudaGetSymbolAddress((void**)&GT,   g_GT);
    cudaGetSymbolAddress((void**)&G2,   g_G2);

    const __half* wRh = wh + (size_t)1536 * CDIM;
    const __half* Am  = P;
    const __half* Bm  = P + (size_t)512 * NDIM;

    const size_t sNC = (size_t)NDIM * CDIM;   // 1024*512
    const size_t sCC = (size_t)CDIM * CDIM;   // 512*512
    const size_t sXN = (size_t)CDIM * NDIM;   // 512*1024 (float out stride)

    cudaFuncSetAttribute(hgemm_nt_kernel<true,  false>, cudaFuncAttributeMaxDynamicSharedMemorySize, HGEMM_SMEM);
    cudaFuncSetAttribute(hgemm_nt_kernel<false, false>, cudaFuncAttributeMaxDynamicSharedMemorySize, HGEMM_SMEM);
    cudaFuncSetAttribute(hgemm_nt_kernel<true,  true >, cudaFuncAttributeMaxDynamicSharedMemorySize, HGEMM_SMEM);

    dim3 blk(256);

    // 0) conversions: x -> xh (transpose+half), weights -> wh, bias stack
    {
        dim3 g(NDIM / 32, CDIM / 32, BSZ), b(32, 8);
        tconv_x_kernel<<<g, b>>>(x, xh);
        dim3 gw((CDIM * CDIM + 255) / 256, 5);
        wconv_kernel<<<gw, blk>>>(wA, wB, wV, wR, bA, bB, bV, wh, bias);
    }

    // 1) P = Wh (.) xh^T + bias   M=1536, N=1024, K=512, half out
    {
        dim3 g(NDIM / 128, MSTK / 128, BSZ);
        hgemm_nt_kernel<true, false><<<g, blk, HGEMM_SMEM>>>(
            wh, 0, CDIM, xh, sNC, CDIM, bias, P, PSTRIDE, NDIM, CDIM);
    }

    // 2) softmax on Bm, Vm rows
    {
        dim3 g(BSZ * CDIM, 2);
        softmax_rows_kernel<<<g, blk>>>(P);
    }

    // 3) VmT = transpose(Vm)
    {
        dim3 g(NDIM / 32, CDIM / 32, BSZ), b(32, 8);
        tconv_v_kernel<<<g, b>>>(P, VmT);
    }

    // 4) GT[d][c] = Bm (.) Am^T   M=N=512, K=1024, half out
    {
        dim3 g(CDIM / 128, CDIM / 128, BSZ);
        hgemm_nt_kernel<false, false><<<g, blk, HGEMM_SMEM>>>(
            Bm, PSTRIDE, NDIM, Am, PSTRIDE, NDIM, nullptr, GT, sCC, CDIM, NDIM);
    }

    // 5) G2[o][d] = wRh (.) GT^T  M=N=K=512, half out
    {
        dim3 g(CDIM / 128, CDIM / 128, BSZ);
        hgemm_nt_kernel<false, false><<<g, blk, HGEMM_SMEM>>>(
            wRh, 0, CDIM, GT, sCC, CDIM, nullptr, G2, sCC, CDIM, CDIM);
    }

    // 6) out[o][n] = G2 (.) VmT^T + bR   M=512, N=1024, K=512, float out
    {
        dim3 g(NDIM / 128, CDIM / 128, BSZ);
        hgemm_nt_kernel<true, true><<<g, blk, HGEMM_SMEM>>>(
            G2, sCC, CDIM, VmT, sNC, CDIM, bR, out, sXN, NDIM, CDIM);
    }
}

// round 17
// speedup vs baseline: 2.5560x; 1.0510x over previous
#include <cuda_runtime.h>
#include <cuda_fp16.h>
#include <cstdint>

// ---------------------------------------------------------------------------
// DoubleAttention, R9b (compile fix): fp16 mma.m16n8k16 (fp32 accum),
// 3-stage cp.async pipeline (96KB dynamic, 2 CTAs/SM), warp-per-row softmax.
// Dataflow identical to R8 (all-NT, half operands).
// ---------------------------------------------------------------------------

#define BSZ   32
#define CDIM  512
#define NDIM  1024
#define MSTK  1536
#define PSTRIDE ((size_t)MSTK * NDIM)

__device__ __half g_xh [(size_t)BSZ * NDIM * CDIM];
__device__ __half g_wh [(size_t)2048 * CDIM];
__device__ float  g_bias[MSTK];
__device__ __half g_P  [(size_t)BSZ * MSTK * NDIM];
__device__ __half g_VmT[(size_t)BSZ * NDIM * CDIM];
__device__ __half g_GT [(size_t)BSZ * CDIM * CDIM];
__device__ __half g_G2 [(size_t)BSZ * CDIM * CDIM];

__device__ __forceinline__ uint32_t smem_u32(const void* p) {
    uint32_t a;
    asm("{ .reg .u64 t; cvta.to.shared.u64 t, %1; cvt.u32.u64 %0, t; }"
        : "=r"(a) : "l"(p));
    return a;
}
__device__ __forceinline__ void cp16(uint32_t dst, const void* src) {
    asm volatile("cp.async.cg.shared.global [%0], [%1], 16;"
                 :: "r"(dst), "l"(src));
}

#define LDSM4(r, a) \
    asm volatile("ldmatrix.sync.aligned.m8n8.x4.shared.b16 {%0,%1,%2,%3}, [%4];" \
                 : "=r"((r)[0]), "=r"((r)[1]), "=r"((r)[2]), "=r"((r)[3]) : "r"(a))

#define HMMA(c, a, b0v, b1v) \
    asm volatile("mma.sync.aligned.m16n8k16.row.col.f32.f16.f16.f32 " \
                 "{%0,%1,%2,%3}, {%4,%5,%6,%7}, {%8,%9}, {%0,%1,%2,%3};" \
                 : "+f"((c)[0]), "+f"((c)[1]), "+f"((c)[2]), "+f"((c)[3]) \
                 : "r"((a)[0]), "r"((a)[1]), "r"((a)[2]), "r"((a)[3]), \
                   "r"(b0v), "r"(b1v))

// ---------------------------------------------------------------------------
// Conversions / transposes
// ---------------------------------------------------------------------------
__global__ __launch_bounds__(256)
void tconv_x_kernel(const float* __restrict__ x, __half* __restrict__ xh)
{
    __shared__ float t[32][33];
    const int tx = threadIdx.x, ty = threadIdx.y;
    const int n0 = blockIdx.x * 32, c0 = blockIdx.y * 32;
    const float* in = x + (size_t)blockIdx.z * CDIM * NDIM;
    __half* out = xh + (size_t)blockIdx.z * NDIM * CDIM;
#pragma unroll
    for (int i = 0; i < 4; i++)
        t[ty + i * 8][tx] = in[(size_t)(c0 + ty + i * 8) * NDIM + n0 + tx];
    __syncthreads();
#pragma unroll
    for (int i = 0; i < 4; i++)
        out[(size_t)(n0 + ty + i * 8) * CDIM + c0 + tx] =
            __float2half_rn(t[tx][ty + i * 8]);
}

__global__ __launch_bounds__(256)
void tconv_v_kernel(const __half* __restrict__ P, __half* __restrict__ VmT)
{
    __shared__ __half t[32][33];
    const int tx = threadIdx.x, ty = threadIdx.y;
    const int n0 = blockIdx.x * 32, d0 = blockIdx.y * 32;
    const __half* in = P + (size_t)blockIdx.z * PSTRIDE + (size_t)1024 * NDIM;
    __half* out = VmT + (size_t)blockIdx.z * NDIM * CDIM;
#pragma unroll
    for (int i = 0; i < 4; i++)
        t[ty + i * 8][tx] = in[(size_t)(d0 + ty + i * 8) * NDIM + n0 + tx];
    __syncthreads();
#pragma unroll
    for (int i = 0; i < 4; i++)
        out[(size_t)(n0 + ty + i * 8) * CDIM + d0 + tx] = t[tx][ty + i * 8];
}

__global__ __launch_bounds__(256)
void wconv_kernel(const float* w0, const float* w1,
                  const float* w2, const float* w3,
                  const float* b0, const float* b1, const float* b2,
                  __half* __restrict__ wh, float* __restrict__ bias)
{
    const int y = blockIdx.y;
    const int i = blockIdx.x * 256 + threadIdx.x;
    if (y < 4) {
        const float* srcs[4] = { w0, w1, w2, w3 };
        if (i < CDIM * CDIM)
            wh[(size_t)y * CDIM * CDIM + i] = __float2half_rn(srcs[y][i]);
    } else {
        if (i < MSTK) {
            float v = (i < 512) ? b0[i] : (i < 1024) ? b1[i - 512] : b2[i - 1024];
            bias[i] = v;
        }
    }
}

// ---------------------------------------------------------------------------
// fp16 NT GEMM, 3-stage cp.async (96KB dynamic), 2 CTAs/SM.
// ---------------------------------------------------------------------------
#define HSTG 32768
#define HGEMM_SMEM (3 * HSTG)

template<bool BIAS, bool OUTF>
__global__ void __launch_bounds__(256, 2)
hgemm_nt_kernel(const __half* __restrict__ Ag, size_t sAs, int lda,
                const __half* __restrict__ Bg, size_t sBs, int ldb,
                const float* __restrict__ bias,
                void* __restrict__ Cg, size_t sCs, int ldc, int K)
{
    extern __shared__ char smem[];
    const uint32_t sbase = smem_u32(smem);

    const int tid  = threadIdx.x;
    const int lane = tid & 31;
    const int wid  = tid >> 5;
    const int m0   = (wid & 1) * 64;
    const int n0   = (wid >> 1) * 32;
    const int row0 = blockIdx.y * 128;
    const int col0 = blockIdx.x * 128;

    const __half* A = Ag + (size_t)blockIdx.z * sAs;
    const __half* B = Bg + (size_t)blockIdx.z * sBs;

    float acc[4][4][4];
#pragma unroll
    for (int i = 0; i < 4; i++)
#pragma unroll
        for (int j = 0; j < 4; j++)
#pragma unroll
            for (int r = 0; r < 4; r++) acc[i][j][r] = 0.f;

    const int nch = K >> 6;

    auto load_stage = [&](int s, int k0) {
        const uint32_t bA = sbase + (uint32_t)s * HSTG;
        const uint32_t bB = bA + 16384u;
#pragma unroll
        for (int i = 0; i < 4; i++) {
            const int idx = tid + i * 256;
            const int r  = idx >> 3;
            const int cc = idx & 7;
            const int sw = cc ^ (r & 7);
            cp16(bA + (uint32_t)(r * 128 + sw * 16),
                 A + (size_t)(row0 + r) * lda + k0 + cc * 8);
            cp16(bB + (uint32_t)(r * 128 + sw * 16),
                 B + (size_t)(col0 + r) * ldb + k0 + cc * 8);
        }
        asm volatile("cp.async.commit_group;" ::: "memory");
    };

    load_stage(0, 0);
    load_stage(1, 64);

    const int l7  = lane & 7;
    const uint32_t aRowOff = (uint32_t)(m0 + (lane & 15)) * 128;
    const int aHi = lane >> 4;
    const uint32_t bRowOff = (uint32_t)(n0 + l7 + ((lane >> 4) << 3)) * 128;
    const int bHi = (lane >> 3) & 1;

    for (int ch = 0; ch < nch; ++ch) {
        const int s = ch % 3;
        if (ch + 1 < nch)
            asm volatile("cp.async.wait_group 1;" ::: "memory");
        else
            asm volatile("cp.async.wait_group 0;" ::: "memory");
        __syncthreads();

        if (ch + 2 < nch) load_stage((ch + 2) % 3, (ch + 2) << 6);

        const uint32_t stA = sbase + (uint32_t)s * HSTG;
        const uint32_t stB = stA + 16384u;

#pragma unroll
        for (int ks = 0; ks < 4; ks++) {
            const uint32_t swA = (uint32_t)(((2 * ks + aHi) ^ l7) * 16);
            const uint32_t swB = (uint32_t)(((2 * ks + bHi) ^ l7) * 16);

            uint32_t aF[4][4];
#pragma unroll
            for (int mi = 0; mi < 4; mi++)
                LDSM4(aF[mi], stA + aRowOff + mi * 2048 + swA);

            uint32_t bF[4][2];
            {
                uint32_t t0[4], t1[4];
                LDSM4(t0, stB + bRowOff + swB);
                LDSM4(t1, stB + bRowOff + 2048 + swB);
                bF[0][0] = t0[0]; bF[0][1] = t0[1];
                bF[1][0] = t0[2]; bF[1][1] = t0[3];
                bF[2][0] = t1[0]; bF[2][1] = t1[1];
                bF[3][0] = t1[2]; bF[3][1] = t1[3];
            }
#pragma unroll
            for (int nj = 0; nj < 4; nj++)
#pragma unroll
                for (int mi = 0; mi < 4; mi++)
                    HMMA(acc[mi][nj], aF[mi], bF[nj][0], bF[nj][1]);
        }
        __syncthreads();
    }

    const int lr = lane >> 2;
    const int lc = lane & 3;
#pragma unroll
    for (int mi = 0; mi < 4; mi++) {
        const int r = row0 + m0 + mi * 16 + lr;
        const float bv0 = BIAS ? bias[r]     : 0.f;
        const float bv8 = BIAS ? bias[r + 8] : 0.f;
#pragma unroll
        for (int nj = 0; nj < 4; nj++) {
            const int c = col0 + n0 + nj * 8 + lc * 2;
            const float v00 = acc[mi][nj][0] + bv0;
            const float v01 = acc[mi][nj][1] + bv0;
            const float v80 = acc[mi][nj][2] + bv8;
            const float v81 = acc[mi][nj][3] + bv8;
            if (OUTF) {
                float* C = (float*)Cg + (size_t)blockIdx.z * sCs;
                *(float2*)(C + (size_t)r * ldc + c)       = make_float2(v00, v01);
                *(float2*)(C + (size_t)(r + 8) * ldc + c) = make_float2(v80, v81);
            } else {
                __half* C = (__half*)Cg + (size_t)blockIdx.z * sCs;
                *(__half2*)(C + (size_t)r * ldc + c)       = __floats2half2_rn(v00, v01);
                *(__half2*)(C + (size_t)(r + 8) * ldc + c) = __floats2half2_rn(v80, v81);
            }
        }
    }
}

// ---------------------------------------------------------------------------
// Warp-per-row softmax: 8 rows/block, pure shfl reductions, no barriers.
// Each lane: 32 halves = 4 x 16B vector loads. fp32 math, half output.
// ---------------------------------------------------------------------------
__global__ __launch_bounds__(256)
void softmax_rows_kernel(__half* __restrict__ P)
{
    const int w    = threadIdx.x >> 5;
    const int lane = threadIdx.x & 31;
    const int gr   = blockIdx.x * 8 + w;       // 0 .. 16383
    const int batch = gr >> 9;
    const int rin   = gr & 511;
    __half* row = P + (size_t)batch * PSTRIDE
                    + (size_t)(512 + (blockIdx.y << 9) + rin) * NDIM;

    uint4* rv = (uint4*)row;                   // 128 x 16B chunks per row
    uint4 d[4];
#pragma unroll
    for (int i = 0; i < 4; i++)
        d[i] = rv[lane + i * 32];

    float f[32];
#pragma unroll
    for (int i = 0; i < 4; i++) {
        const __half2* h2 = (const __half2*)&d[i];
#pragma unroll
        for (int j = 0; j < 4; j++) {
            float2 ff = __half22float2(h2[j]);
            f[i * 8 + j * 2]     = ff.x;
            f[i * 8 + j * 2 + 1] = ff.y;
        }
    }

    float m = f[0];
#pragma unroll
    for (int i = 1; i < 32; i++) m = fmaxf(m, f[i]);
#pragma unroll
    for (int o = 16; o > 0; o >>= 1)
        m = fmaxf(m, __shfl_xor_sync(0xffffffffu, m, o));

    float s = 0.f;
#pragma unroll
    for (int i = 0; i < 32; i++) {
        f[i] = __expf(f[i] - m);
        s += f[i];
    }
#pragma unroll
    for (int o = 16; o > 0; o >>= 1)
        s += __shfl_xor_sync(0xffffffffu, s, o);
    const float inv = 1.0f / s;

#pragma unroll
    for (int i = 0; i < 4; i++) {
        __half2* h2 = (__half2*)&d[i];
#pragma unroll
        for (int j = 0; j < 4; j++)
            h2[j] = __floats2half2_rn(f[i * 8 + j * 2] * inv,
                                      f[i * 8 + j * 2 + 1] * inv);
        rv[lane + i * 32] = d[i];
    }
}

// ---------------------------------------------------------------------------
extern "C" void kernel_launch(void* const* d_in, const int* in_sizes, int n_in,
                              void* d_out, int out_size)
{
    const float* x  = (const float*)d_in[0];
    const float* wA = (const float*)d_in[1];
    const float* bA = (const float*)d_in[2];
    const float* wB = (const float*)d_in[3];
    const float* bB = (const float*)d_in[4];
    const float* wV = (const float*)d_in[5];
    const float* bV = (const float*)d_in[6];
    const float* wR = (const float*)d_in[7];
    const float* bR = (const float*)d_in[8];
    float* out = (float*)d_out;

    __half *xh, *wh, *P, *VmT, *GT, *G2;
    float *bias;
    cudaGetSymbolAddress((void**)&xh,   g_xh);
    cudaGetSymbolAddress((void**)&wh,   g_wh);
    cudaGetSymbolAddress((void**)&bias, g_bias);
    cudaGetSymbolAddress((void**)&P,    g_P);
    cudaGetSymbolAddress((void**)&VmT,  g_VmT);
    cudaGetSymbolAddress((void**)&GT,   g_GT);
    cudaGetSymbolAddress((void**)&G2,   g_G2);

    const __half* wRh = wh + (size_t)1536 * CDIM;
    const __half* Am  = P;
    const __half* Bm  = P + (size_t)512 * NDIM;

    const size_t sNC = (size_t)NDIM * CDIM;
    const size_t sCC = (size_t)CDIM * CDIM;
    const size_t sXN = (size_t)CDIM * NDIM;

    cudaFuncSetAttribute(hgemm_nt_kernel<true,  false>, cudaFuncAttributeMaxDynamicSharedMemorySize, HGEMM_SMEM);
    cudaFuncSetAttribute(hgemm_nt_kernel<false, false>, cudaFuncAttributeMaxDynamicSharedMemorySize, HGEMM_SMEM);
    cudaFuncSetAttribute(hgemm_nt_kernel<true,  true >, cudaFuncAttributeMaxDynamicSharedMemorySize, HGEMM_SMEM);

    dim3 blk(256);

    // 0) conversions
    {
        dim3 g(NDIM / 32, CDIM / 32, BSZ), b(32, 8);
        tconv_x_kernel<<<g, b>>>(x, xh);
        dim3 gw((CDIM * CDIM + 255) / 256, 5);
        wconv_kernel<<<gw, blk>>>(wA, wB, wV, wR, bA, bB, bV, wh, bias);
    }

    // 1) P = Wh (.) xh^T + bias   M=1536, N=1024, K=512
    {
        dim3 g(NDIM / 128, MSTK / 128, BSZ);
        hgemm_nt_kernel<true, false><<<g, blk, HGEMM_SMEM>>>(
            wh, 0, CDIM, xh, sNC, CDIM, bias, P, PSTRIDE, NDIM, CDIM);
    }

    // 2) softmax on Bm, Vm rows (warp-per-row)
    {
        dim3 g(BSZ * CDIM / 8, 2);
        softmax_rows_kernel<<<g, blk>>>(P);
    }

    // 3) VmT = transpose(Vm)
    {
        dim3 g(NDIM / 32, CDIM / 32, BSZ), b(32, 8);
        tconv_v_kernel<<<g, b>>>(P, VmT);
    }

    // 4) GT = Bm (.) Am^T   M=N=512, K=1024
    {
        dim3 g(CDIM / 128, CDIM / 128, BSZ);
        hgemm_nt_kernel<false, false><<<g, blk, HGEMM_SMEM>>>(
            Bm, PSTRIDE, NDIM, Am, PSTRIDE, NDIM, nullptr, GT, sCC, CDIM, NDIM);
    }

    // 5) G2 = wRh (.) GT^T  M=N=K=512
    {
        dim3 g(CDIM / 128, CDIM / 128, BSZ);
        hgemm_nt_kernel<false, false><<<g, blk, HGEMM_SMEM>>>(
            wRh, 0, CDIM, GT, sCC, CDIM, nullptr, G2, sCC, CDIM, CDIM);
    }

    // 6) out = G2 (.) VmT^T + bR   M=512, N=1024, K=512, float out
    {
        dim3 g(NDIM / 128, CDIM / 128, BSZ);
        hgemm_nt_kernel<true, true><<<g, blk, HGEMM_SMEM>>>(
            G2, sCC, CDIM, VmT, sNC, CDIM, bR, out, sXN, NDIM, CDIM);
    }
}